// round 7
// baseline (speedup 1.0000x reference)
#include <cuda_runtime.h>
#include <math.h>
#include <stdint.h>

#define NJ 24
#define POSE_STRIDE (NJ * 3)
#define GROW 12            // floats per joint: [R00 R01 R02 t0 | R10 R11 R12 t1 | R20 R21 R22 t2]
#define MAX_B 1024
#define NB 8               // batches per skinning block
#define VT 128             // threads per skinning block
#define VPT 4              // vertices per thread (amortize broadcast G delivery)

__constant__ int c_par[NJ] = {-1, 0, 0, 0, 1, 2, 3, 4, 5, 6, 7, 8, 9, 9, 9,
                              12, 13, 14, 16, 17, 18, 19, 20, 21};

// scratch: per-batch final transforms, 24 joints x 12 floats (no allocation)
__device__ float g_G[MAX_B * NJ * GROW];

// ---------------- packed f32x2 helpers (sm_100-family only) ----------------
__device__ __forceinline__ uint64_t packf2(float lo, float hi) {
    uint64_t r;
    asm("mov.b64 %0, {%1, %2};" : "=l"(r) : "f"(lo), "f"(hi));
    return r;
}
__device__ __forceinline__ void fma2(uint64_t& a, uint64_t b, uint64_t c) {
    // a = b * c + a  (two independent fp32 lanes)
    asm("fma.rn.f32x2 %0, %1, %2, %0;" : "+l"(a) : "l"(b), "l"(c));
}
__device__ __forceinline__ void unpackf2(uint64_t p, float& lo, float& hi) {
    asm("mov.b64 {%0, %1}, %2;" : "=f"(lo), "=f"(hi) : "l"(p));
}

// ---------------------------------------------------------------------------
// Kernel 1: forward kinematics. One block per batch (32 threads).
// ---------------------------------------------------------------------------
__global__ void fk_kernel(const float* __restrict__ pose,
                          const float* __restrict__ J_hat, int B) {
    int b = blockIdx.x;
    if (b >= B) return;
    __shared__ float Gs[NJ][GROW];

    int t = threadIdx.x;
    if (t < NJ) {
        float rx = pose[b * POSE_STRIDE + t * 3 + 0];
        float ry = pose[b * POSE_STRIDE + t * 3 + 1];
        float rz = pose[b * POSE_STRIDE + t * 3 + 2];
        float theta = sqrtf(rx * rx + ry * ry + rz * rz) + 1e-8f;
        float inv = 1.0f / theta;
        float ux = rx * inv, uy = ry * inv, uz = rz * inv;
        float c = cosf(theta);
        float s = sinf(theta);
        float ic = 1.0f - c;

        int p = c_par[t];
        float jx = J_hat[t * 3 + 0];
        float jy = J_hat[t * 3 + 1];
        float jz = J_hat[t * 3 + 2];
        if (p >= 0) {
            jx -= J_hat[p * 3 + 0];
            jy -= J_hat[p * 3 + 1];
            jz -= J_hat[p * 3 + 2];
        }

        Gs[t][0]  = c + ic * ux * ux;
        Gs[t][1]  = ic * ux * uy - s * uz;
        Gs[t][2]  = ic * ux * uz + s * uy;
        Gs[t][3]  = jx;
        Gs[t][4]  = ic * uy * ux + s * uz;
        Gs[t][5]  = c + ic * uy * uy;
        Gs[t][6]  = ic * uy * uz - s * ux;
        Gs[t][7]  = jy;
        Gs[t][8]  = ic * uz * ux - s * uy;
        Gs[t][9]  = ic * uz * uy + s * ux;
        Gs[t][10] = c + ic * uz * uz;
        Gs[t][11] = jz;
    }
    __syncthreads();

    if (t == 0) {
        for (int i = 1; i < NJ; i++) {
            int p = c_par[i];
            float tmp[GROW];
            #pragma unroll
            for (int x = 0; x < 3; x++) {
                float p0 = Gs[p][x * 4 + 0];
                float p1 = Gs[p][x * 4 + 1];
                float p2 = Gs[p][x * 4 + 2];
                float p3 = Gs[p][x * 4 + 3];
                tmp[x * 4 + 0] = p0 * Gs[i][0] + p1 * Gs[i][4] + p2 * Gs[i][8];
                tmp[x * 4 + 1] = p0 * Gs[i][1] + p1 * Gs[i][5] + p2 * Gs[i][9];
                tmp[x * 4 + 2] = p0 * Gs[i][2] + p1 * Gs[i][6] + p2 * Gs[i][10];
                tmp[x * 4 + 3] = p0 * Gs[i][3] + p1 * Gs[i][7] + p2 * Gs[i][11] + p3;
            }
            #pragma unroll
            for (int k = 0; k < GROW; k++) Gs[i][k] = tmp[k];
        }
    }
    __syncthreads();

    if (t < NJ) {
        float jx = J_hat[t * 3 + 0];
        float jy = J_hat[t * 3 + 1];
        float jz = J_hat[t * 3 + 2];
        Gs[t][3]  -= Gs[t][0] * jx + Gs[t][1]  * jy + Gs[t][2]  * jz;
        Gs[t][7]  -= Gs[t][4] * jx + Gs[t][5]  * jy + Gs[t][6]  * jz;
        Gs[t][11] -= Gs[t][8] * jx + Gs[t][9]  * jy + Gs[t][10] * jz;
    }
    __syncthreads();

    const float* src = &Gs[0][0];
    float* dst = g_G + (size_t)b * NJ * GROW;
    for (int i = t; i < NJ * GROW; i += blockDim.x) dst[i] = src[i];
}

// ---------------------------------------------------------------------------
// Kernel 2: LBS. Block covers VT*VPT vertices x NB batches.
// Each broadcast G load (3x LDS.128 per joint) feeds 4 vertices' packed FMAs.
// ---------------------------------------------------------------------------
__global__ __launch_bounds__(VT, 2)
void skin_kernel(const float* __restrict__ T_hat,
                 const float* __restrict__ W,
                 const float* __restrict__ trans,
                 float* __restrict__ out, int V, int B) {
    __shared__ ulonglong2 Gs[NB * NJ * 3];   // NB x 24 joints x 12 floats (16B chunks)
    __shared__ float ts[NB * 3];

    int b0 = blockIdx.y * NB;
    int nb = min(NB, B - b0);

    {
        const ulonglong2* gsrc =
            reinterpret_cast<const ulonglong2*>(g_G + (size_t)b0 * NJ * GROW);
        int n = nb * NJ * 3;
        for (int i = threadIdx.x; i < n; i += VT) Gs[i] = gsrc[i];
        if (threadIdx.x < nb * 3) ts[threadIdx.x] = trans[b0 * 3 + threadIdx.x];
    }
    __syncthreads();

    int vbase = blockIdx.x * (VT * VPT) + threadIdx.x;
    int v[VPT];
    bool ok[VPT];
    #pragma unroll
    for (int u = 0; u < VPT; u++) {
        v[u] = vbase + u * VT;
        ok[u] = v[u] < V;
    }
    if (!ok[0]) return;   // later vertices are larger, all inactive too
    int vc[VPT];
    #pragma unroll
    for (int u = 0; u < VPT; u++) vc[u] = ok[u] ? v[u] : v[0];

    // per-vertex weights (24 floats each, row stride 96 B -> 16B aligned)
    float w[VPT][NJ];
    #pragma unroll
    for (int u = 0; u < VPT; u++) {
        const float4* w4 = reinterpret_cast<const float4*>(W + (size_t)vc[u] * NJ);
        #pragma unroll
        for (int q = 0; q < NJ / 4; q++) {
            float4 f = w4[q];
            w[u][q * 4 + 0] = f.x; w[u][q * 4 + 1] = f.y;
            w[u][q * 4 + 2] = f.z; w[u][q * 4 + 3] = f.w;
        }
    }
    float px[VPT], py[VPT], pz[VPT];
    #pragma unroll
    for (int u = 0; u < VPT; u++) {
        px[u] = T_hat[vc[u] * 3 + 0];
        py[u] = T_hat[vc[u] * 3 + 1];
        pz[u] = T_hat[vc[u] * 3 + 2];
    }

    for (int bb = 0; bb < nb; bb++) {
        uint64_t acc[VPT][6];
        #pragma unroll
        for (int u = 0; u < VPT; u++)
            #pragma unroll
            for (int k = 0; k < 6; k++) acc[u][k] = 0ull;

        const ulonglong2* g = Gs + bb * NJ * 3;
        #pragma unroll
        for (int j = 0; j < NJ; j++) {
            ulonglong2 q0 = g[j * 3 + 0];   // floats 0..3
            ulonglong2 q1 = g[j * 3 + 1];   // floats 4..7
            ulonglong2 q2 = g[j * 3 + 2];   // floats 8..11
            #pragma unroll
            for (int u = 0; u < VPT; u++) {
                uint64_t wj = packf2(w[u][j], w[u][j]);
                fma2(acc[u][0], q0.x, wj);
                fma2(acc[u][1], q0.y, wj);
                fma2(acc[u][2], q1.x, wj);
                fma2(acc[u][3], q1.y, wj);
                fma2(acc[u][4], q2.x, wj);
                fma2(acc[u][5], q2.y, wj);
            }
        }

        float tx = ts[bb * 3 + 0], ty = ts[bb * 3 + 1], tz = ts[bb * 3 + 2];

        #pragma unroll
        for (int u = 0; u < VPT; u++) {
            if (!ok[u]) continue;
            float a0, a1, a2, a3, a4, a5, a6, a7, a8, a9, a10, a11;
            unpackf2(acc[u][0], a0, a1);  unpackf2(acc[u][1], a2, a3);
            unpackf2(acc[u][2], a4, a5);  unpackf2(acc[u][3], a6, a7);
            unpackf2(acc[u][4], a8, a9);  unpackf2(acc[u][5], a10, a11);
            float ox = a0 * px[u] + a1 * py[u] + a2  * pz[u] + a3  + tx;
            float oy = a4 * px[u] + a5 * py[u] + a6  * pz[u] + a7  + ty;
            float oz = a8 * px[u] + a9 * py[u] + a10 * pz[u] + a11 + tz;
            float* o = out + ((size_t)(b0 + bb) * V + v[u]) * 3;
            o[0] = ox; o[1] = oy; o[2] = oz;
        }
    }
}

// ---------------------------------------------------------------------------
// Launch: pure kernel launches only (graph-capture safe).
// ---------------------------------------------------------------------------
extern "C" void kernel_launch(void* const* d_in, const int* in_sizes, int n_in,
                              void* d_out, int out_size) {
    const float* T_hat   = (const float*)d_in[0];   // (V,3)
    const float* J_hat   = (const float*)d_in[1];   // (24,3)
    const float* weights = (const float*)d_in[2];   // (V,24)
    const float* pose    = (const float*)d_in[3];   // (B,72)
    const float* trans   = (const float*)d_in[4];   // (B,3)
    float* out = (float*)d_out;

    int V = in_sizes[0] / 3;
    int B = in_sizes[3] / POSE_STRIDE;
    if (B > MAX_B) B = MAX_B;

    fk_kernel<<<B, 32>>>(pose, J_hat, B);

    dim3 grid((V + VT * VPT - 1) / (VT * VPT), (B + NB - 1) / NB);
    skin_kernel<<<grid, VT>>>(T_hat, weights, trans, out, V, B);
}